// round 8
// baseline (speedup 1.0000x reference)
#include <cuda_runtime.h>
#include <cuda_bf16.h>

// Masked mean: mean of (x - y) where x > y, over 32M fp32 elements.
// R8: contiguous per-CTA chunks (DRAM row / L2-slice / TLB locality)
// instead of chip-wide grid-stride. 1216 CTAs (152 SMs x 8) x 256 thr,
// 4x-unrolled block-stride within chunk, front-batched 4+4 LDG.128
// bursts, __ldcs streaming. Last-block-done finalize with self-resetting
// __device__ globals (graph-replay safe, single launch).

__device__ float               g_sum;     // zero-initialized at load
__device__ unsigned long long  g_cnt;
__device__ unsigned int        g_ticket;

__global__ __launch_bounds__(256) void fused_reduce_kernel(
    const float4* __restrict__ x4,
    const float4* __restrict__ y4,
    int n4,
    float* __restrict__ out)
{
    float fs0 = 0.0f, fs1 = 0.0f;
    unsigned int cnt = 0;

    // contiguous chunk for this CTA
    const int chunk = (n4 + gridDim.x - 1) / gridDim.x;
    const int beg   = blockIdx.x * chunk;
    const int end   = min(beg + chunk, n4);
    const int bstep = blockDim.x;          // 256 float4s = 4 KB per step

    int i = beg + threadIdx.x;

    // main loop: 4x unrolled within the CTA's contiguous chunk
    for (; i + 3 * bstep < end; i += 4 * bstep) {
        float4 xa = __ldcs(&x4[i]);
        float4 xb = __ldcs(&x4[i +     bstep]);
        float4 xc = __ldcs(&x4[i + 2 * bstep]);
        float4 xd = __ldcs(&x4[i + 3 * bstep]);
        float4 ya = __ldcs(&y4[i]);
        float4 yb = __ldcs(&y4[i +     bstep]);
        float4 yc = __ldcs(&y4[i + 2 * bstep]);
        float4 yd = __ldcs(&y4[i + 3 * bstep]);

        float a0 = xa.x - ya.x, a1 = xa.y - ya.y, a2 = xa.z - ya.z, a3 = xa.w - ya.w;
        float b0 = xb.x - yb.x, b1 = xb.y - yb.y, b2 = xb.z - yb.z, b3 = xb.w - yb.w;
        float c0 = xc.x - yc.x, c1 = xc.y - yc.y, c2 = xc.z - yc.z, c3 = xc.w - yc.w;
        float e0 = xd.x - yd.x, e1 = xd.y - yd.y, e2 = xd.z - yd.z, e3 = xd.w - yd.w;

        fs0 += fmaxf(a0, 0.0f) + fmaxf(a1, 0.0f) + fmaxf(a2, 0.0f) + fmaxf(a3, 0.0f);
        fs1 += fmaxf(b0, 0.0f) + fmaxf(b1, 0.0f) + fmaxf(b2, 0.0f) + fmaxf(b3, 0.0f);
        fs0 += fmaxf(c0, 0.0f) + fmaxf(c1, 0.0f) + fmaxf(c2, 0.0f) + fmaxf(c3, 0.0f);
        fs1 += fmaxf(e0, 0.0f) + fmaxf(e1, 0.0f) + fmaxf(e2, 0.0f) + fmaxf(e3, 0.0f);

        cnt += (a0 > 0.0f) + (a1 > 0.0f) + (a2 > 0.0f) + (a3 > 0.0f)
             + (b0 > 0.0f) + (b1 > 0.0f) + (b2 > 0.0f) + (b3 > 0.0f)
             + (c0 > 0.0f) + (c1 > 0.0f) + (c2 > 0.0f) + (c3 > 0.0f)
             + (e0 > 0.0f) + (e1 > 0.0f) + (e2 > 0.0f) + (e3 > 0.0f);
    }

    // tail
    for (; i < end; i += bstep) {
        float4 xv = __ldcs(&x4[i]);
        float4 yv = __ldcs(&y4[i]);
        float d0 = xv.x - yv.x, d1 = xv.y - yv.y;
        float d2 = xv.z - yv.z, d3 = xv.w - yv.w;
        fs0 += fmaxf(d0, 0.0f) + fmaxf(d1, 0.0f)
             + fmaxf(d2, 0.0f) + fmaxf(d3, 0.0f);
        cnt += (d0 > 0.0f) + (d1 > 0.0f) + (d2 > 0.0f) + (d3 > 0.0f);
    }

    float fsum = fs0 + fs1;

    // warp reduce
    #pragma unroll
    for (int off = 16; off > 0; off >>= 1) {
        fsum += __shfl_down_sync(0xFFFFFFFFu, fsum, off);
        cnt  += __shfl_down_sync(0xFFFFFFFFu, cnt,  off);
    }

    __shared__ float        s_sum[8];
    __shared__ unsigned int s_cnt[8];
    __shared__ bool         s_last;
    int lane = threadIdx.x & 31;
    int wid  = threadIdx.x >> 5;
    if (lane == 0) { s_sum[wid] = fsum; s_cnt[wid] = cnt; }
    __syncthreads();

    if (wid == 0) {
        fsum = (lane < 8) ? s_sum[lane] : 0.0f;
        cnt  = (lane < 8) ? s_cnt[lane] : 0u;
        #pragma unroll
        for (int off = 4; off > 0; off >>= 1) {
            fsum += __shfl_down_sync(0xFFFFFFFFu, fsum, off);
            cnt  += __shfl_down_sync(0xFFFFFFFFu, cnt,  off);
        }
        if (lane == 0) {
            atomicAdd(&g_sum, fsum);
            atomicAdd(&g_cnt, (unsigned long long)cnt);
            __threadfence();
            unsigned int t = atomicAdd(&g_ticket, 1u);
            s_last = (t == gridDim.x - 1);
        }
    }
    __syncthreads();

    // Last block: write result, reset globals for next graph replay.
    if (s_last && threadIdx.x == 0) {
        __threadfence();   // make all blocks' atomics visible to this read
        float              fs = g_sum;
        unsigned long long c  = g_cnt;
        out[0] = (c > 0ull) ? (fs / (float)c) : 0.0f;
        g_sum    = 0.0f;
        g_cnt    = 0ull;
        g_ticket = 0u;     // replay boundary orders these before next launch
    }
}

extern "C" void kernel_launch(void* const* d_in, const int* in_sizes, int n_in,
                              void* d_out, int out_size) {
    const float* x = (const float*)d_in[0];
    const float* y = (const float*)d_in[1];
    float* out = (float*)d_out;

    int n  = in_sizes[0];      // 33554432, divisible by 4
    int n4 = n >> 2;

    const int threads = 256;
    const int blocks  = 152 * 8;   // 1216 CTAs -- balanced on GB300's 152 SMs
    fused_reduce_kernel<<<blocks, threads>>>(
        (const float4*)x, (const float4*)y, n4, out);
}

// round 9
// speedup vs baseline: 1.0200x; 1.0200x over previous
#include <cuda_runtime.h>
#include <cuda_bf16.h>

// Masked mean: mean of (x - y) where x > y, over 32M fp32 elements.
// FINAL (R7 config, measured optimum 43.5us, 6293 GB/s ~= LTS chip cap):
// chip-wide grid-stride (best LTS-hash spread; contiguous chunking
// measured WORSE), 1216 CTAs (152 SMs x 8) x 256 thr, 4x-unrolled,
// front-batched x-loads then y-loads (4+4 LDG.128 bursts), __ldcs
// streaming. Last-block-done finalize with self-resetting __device__
// globals (graph-replay safe, single launch).

__device__ float               g_sum;     // zero-initialized at load
__device__ unsigned long long  g_cnt;
__device__ unsigned int        g_ticket;

__global__ __launch_bounds__(256) void fused_reduce_kernel(
    const float4* __restrict__ x4,
    const float4* __restrict__ y4,
    int n4,
    float* __restrict__ out)
{
    float fs0 = 0.0f, fs1 = 0.0f;
    unsigned int cnt = 0;

    const int stride = gridDim.x * blockDim.x;
    int i = blockIdx.x * blockDim.x + threadIdx.x;

    // main loop: 4x unrolled, 4 x-loads batched then 4 y-loads batched
    for (; i + 3 * stride < n4; i += 4 * stride) {
        float4 xa = __ldcs(&x4[i]);
        float4 xb = __ldcs(&x4[i +     stride]);
        float4 xc = __ldcs(&x4[i + 2 * stride]);
        float4 xd = __ldcs(&x4[i + 3 * stride]);
        float4 ya = __ldcs(&y4[i]);
        float4 yb = __ldcs(&y4[i +     stride]);
        float4 yc = __ldcs(&y4[i + 2 * stride]);
        float4 yd = __ldcs(&y4[i + 3 * stride]);

        float a0 = xa.x - ya.x, a1 = xa.y - ya.y, a2 = xa.z - ya.z, a3 = xa.w - ya.w;
        float b0 = xb.x - yb.x, b1 = xb.y - yb.y, b2 = xb.z - yb.z, b3 = xb.w - yb.w;
        float c0 = xc.x - yc.x, c1 = xc.y - yc.y, c2 = xc.z - yc.z, c3 = xc.w - yc.w;
        float e0 = xd.x - yd.x, e1 = xd.y - yd.y, e2 = xd.z - yd.z, e3 = xd.w - yd.w;

        fs0 += fmaxf(a0, 0.0f) + fmaxf(a1, 0.0f) + fmaxf(a2, 0.0f) + fmaxf(a3, 0.0f);
        fs1 += fmaxf(b0, 0.0f) + fmaxf(b1, 0.0f) + fmaxf(b2, 0.0f) + fmaxf(b3, 0.0f);
        fs0 += fmaxf(c0, 0.0f) + fmaxf(c1, 0.0f) + fmaxf(c2, 0.0f) + fmaxf(c3, 0.0f);
        fs1 += fmaxf(e0, 0.0f) + fmaxf(e1, 0.0f) + fmaxf(e2, 0.0f) + fmaxf(e3, 0.0f);

        cnt += (a0 > 0.0f) + (a1 > 0.0f) + (a2 > 0.0f) + (a3 > 0.0f)
             + (b0 > 0.0f) + (b1 > 0.0f) + (b2 > 0.0f) + (b3 > 0.0f)
             + (c0 > 0.0f) + (c1 > 0.0f) + (c2 > 0.0f) + (c3 > 0.0f)
             + (e0 > 0.0f) + (e1 > 0.0f) + (e2 > 0.0f) + (e3 > 0.0f);
    }

    // tail
    for (; i < n4; i += stride) {
        float4 xv = __ldcs(&x4[i]);
        float4 yv = __ldcs(&y4[i]);
        float d0 = xv.x - yv.x, d1 = xv.y - yv.y;
        float d2 = xv.z - yv.z, d3 = xv.w - yv.w;
        fs0 += fmaxf(d0, 0.0f) + fmaxf(d1, 0.0f)
             + fmaxf(d2, 0.0f) + fmaxf(d3, 0.0f);
        cnt += (d0 > 0.0f) + (d1 > 0.0f) + (d2 > 0.0f) + (d3 > 0.0f);
    }

    float fsum = fs0 + fs1;

    // warp reduce
    #pragma unroll
    for (int off = 16; off > 0; off >>= 1) {
        fsum += __shfl_down_sync(0xFFFFFFFFu, fsum, off);
        cnt  += __shfl_down_sync(0xFFFFFFFFu, cnt,  off);
    }

    __shared__ float        s_sum[8];
    __shared__ unsigned int s_cnt[8];
    __shared__ bool         s_last;
    int lane = threadIdx.x & 31;
    int wid  = threadIdx.x >> 5;
    if (lane == 0) { s_sum[wid] = fsum; s_cnt[wid] = cnt; }
    __syncthreads();

    if (wid == 0) {
        fsum = (lane < 8) ? s_sum[lane] : 0.0f;
        cnt  = (lane < 8) ? s_cnt[lane] : 0u;
        #pragma unroll
        for (int off = 4; off > 0; off >>= 1) {
            fsum += __shfl_down_sync(0xFFFFFFFFu, fsum, off);
            cnt  += __shfl_down_sync(0xFFFFFFFFu, cnt,  off);
        }
        if (lane == 0) {
            atomicAdd(&g_sum, fsum);
            atomicAdd(&g_cnt, (unsigned long long)cnt);
            __threadfence();
            unsigned int t = atomicAdd(&g_ticket, 1u);
            s_last = (t == gridDim.x - 1);
        }
    }
    __syncthreads();

    // Last block: write result, reset globals for next graph replay.
    if (s_last && threadIdx.x == 0) {
        __threadfence();   // make all blocks' atomics visible to this read
        float              fs = g_sum;
        unsigned long long c  = g_cnt;
        out[0] = (c > 0ull) ? (fs / (float)c) : 0.0f;
        g_sum    = 0.0f;
        g_cnt    = 0ull;
        g_ticket = 0u;     // replay boundary orders these before next launch
    }
}

extern "C" void kernel_launch(void* const* d_in, const int* in_sizes, int n_in,
                              void* d_out, int out_size) {
    const float* x = (const float*)d_in[0];
    const float* y = (const float*)d_in[1];
    float* out = (float*)d_out;

    int n  = in_sizes[0];      // 33554432, divisible by 4
    int n4 = n >> 2;

    const int threads = 256;
    const int blocks  = 152 * 8;   // 1216 CTAs -- balanced on GB300's 152 SMs
    fused_reduce_kernel<<<blocks, threads>>>(
        (const float4*)x, (const float4*)y, n4, out);
}

// round 10
// speedup vs baseline: 1.0470x; 1.0265x over previous
#include <cuda_runtime.h>
#include <cuda_bf16.h>

// Masked mean: mean of (x - y) where x > y, over 32M fp32 elements.
// FINAL — converged config (best measured 43.5us @ 6293 GB/s ~= LTS chip
// cap; identical source re-measured 44.7us, establishing ~±1.5us DVFS
// noise band — all remaining variation is noise, not structure):
//   * chip-wide grid-stride (uniform LTS-hash spread; contiguous
//     chunking measured WORSE: 75% DRAM)
//   * 1216 CTAs = 152 SMs x 8 (perfect balance on GB300's 152 SMs;
//     1024/1184 grids measured worse), 256 thr/CTA, occ 99.7%
//   * 4x unroll, front-batched 4 x-loads + 4 y-loads (MLP_p1=8;
//     MLP_p1=16 regressed via cross-CTA L1tex queue contention)
//   * __ldcs streaming loads (touch-once data)
//   * single launch: last-block-done finalize, self-resetting
//     __device__ globals (graph-replay safe)

__device__ float               g_sum;     // zero-initialized at load
__device__ unsigned long long  g_cnt;
__device__ unsigned int        g_ticket;

__global__ __launch_bounds__(256) void fused_reduce_kernel(
    const float4* __restrict__ x4,
    const float4* __restrict__ y4,
    int n4,
    float* __restrict__ out)
{
    float fs0 = 0.0f, fs1 = 0.0f;
    unsigned int cnt = 0;

    const int stride = gridDim.x * blockDim.x;
    int i = blockIdx.x * blockDim.x + threadIdx.x;

    // main loop: 4x unrolled, 4 x-loads batched then 4 y-loads batched
    for (; i + 3 * stride < n4; i += 4 * stride) {
        float4 xa = __ldcs(&x4[i]);
        float4 xb = __ldcs(&x4[i +     stride]);
        float4 xc = __ldcs(&x4[i + 2 * stride]);
        float4 xd = __ldcs(&x4[i + 3 * stride]);
        float4 ya = __ldcs(&y4[i]);
        float4 yb = __ldcs(&y4[i +     stride]);
        float4 yc = __ldcs(&y4[i + 2 * stride]);
        float4 yd = __ldcs(&y4[i + 3 * stride]);

        float a0 = xa.x - ya.x, a1 = xa.y - ya.y, a2 = xa.z - ya.z, a3 = xa.w - ya.w;
        float b0 = xb.x - yb.x, b1 = xb.y - yb.y, b2 = xb.z - yb.z, b3 = xb.w - yb.w;
        float c0 = xc.x - yc.x, c1 = xc.y - yc.y, c2 = xc.z - yc.z, c3 = xc.w - yc.w;
        float e0 = xd.x - yd.x, e1 = xd.y - yd.y, e2 = xd.z - yd.z, e3 = xd.w - yd.w;

        fs0 += fmaxf(a0, 0.0f) + fmaxf(a1, 0.0f) + fmaxf(a2, 0.0f) + fmaxf(a3, 0.0f);
        fs1 += fmaxf(b0, 0.0f) + fmaxf(b1, 0.0f) + fmaxf(b2, 0.0f) + fmaxf(b3, 0.0f);
        fs0 += fmaxf(c0, 0.0f) + fmaxf(c1, 0.0f) + fmaxf(c2, 0.0f) + fmaxf(c3, 0.0f);
        fs1 += fmaxf(e0, 0.0f) + fmaxf(e1, 0.0f) + fmaxf(e2, 0.0f) + fmaxf(e3, 0.0f);

        cnt += (a0 > 0.0f) + (a1 > 0.0f) + (a2 > 0.0f) + (a3 > 0.0f)
             + (b0 > 0.0f) + (b1 > 0.0f) + (b2 > 0.0f) + (b3 > 0.0f)
             + (c0 > 0.0f) + (c1 > 0.0f) + (c2 > 0.0f) + (c3 > 0.0f)
             + (e0 > 0.0f) + (e1 > 0.0f) + (e2 > 0.0f) + (e3 > 0.0f);
    }

    // tail
    for (; i < n4; i += stride) {
        float4 xv = __ldcs(&x4[i]);
        float4 yv = __ldcs(&y4[i]);
        float d0 = xv.x - yv.x, d1 = xv.y - yv.y;
        float d2 = xv.z - yv.z, d3 = xv.w - yv.w;
        fs0 += fmaxf(d0, 0.0f) + fmaxf(d1, 0.0f)
             + fmaxf(d2, 0.0f) + fmaxf(d3, 0.0f);
        cnt += (d0 > 0.0f) + (d1 > 0.0f) + (d2 > 0.0f) + (d3 > 0.0f);
    }

    float fsum = fs0 + fs1;

    // warp reduce
    #pragma unroll
    for (int off = 16; off > 0; off >>= 1) {
        fsum += __shfl_down_sync(0xFFFFFFFFu, fsum, off);
        cnt  += __shfl_down_sync(0xFFFFFFFFu, cnt,  off);
    }

    __shared__ float        s_sum[8];
    __shared__ unsigned int s_cnt[8];
    __shared__ bool         s_last;
    int lane = threadIdx.x & 31;
    int wid  = threadIdx.x >> 5;
    if (lane == 0) { s_sum[wid] = fsum; s_cnt[wid] = cnt; }
    __syncthreads();

    if (wid == 0) {
        fsum = (lane < 8) ? s_sum[lane] : 0.0f;
        cnt  = (lane < 8) ? s_cnt[lane] : 0u;
        #pragma unroll
        for (int off = 4; off > 0; off >>= 1) {
            fsum += __shfl_down_sync(0xFFFFFFFFu, fsum, off);
            cnt  += __shfl_down_sync(0xFFFFFFFFu, cnt,  off);
        }
        if (lane == 0) {
            atomicAdd(&g_sum, fsum);
            atomicAdd(&g_cnt, (unsigned long long)cnt);
            __threadfence();
            unsigned int t = atomicAdd(&g_ticket, 1u);
            s_last = (t == gridDim.x - 1);
        }
    }
    __syncthreads();

    // Last block: write result, reset globals for next graph replay.
    if (s_last && threadIdx.x == 0) {
        __threadfence();   // make all blocks' atomics visible to this read
        float              fs = g_sum;
        unsigned long long c  = g_cnt;
        out[0] = (c > 0ull) ? (fs / (float)c) : 0.0f;
        g_sum    = 0.0f;
        g_cnt    = 0ull;
        g_ticket = 0u;     // replay boundary orders these before next launch
    }
}

extern "C" void kernel_launch(void* const* d_in, const int* in_sizes, int n_in,
                              void* d_out, int out_size) {
    const float* x = (const float*)d_in[0];
    const float* y = (const float*)d_in[1];
    float* out = (float*)d_out;

    int n  = in_sizes[0];      // 33554432, divisible by 4
    int n4 = n >> 2;

    const int threads = 256;
    const int blocks  = 152 * 8;   // 1216 CTAs -- balanced on GB300's 152 SMs
    fused_reduce_kernel<<<blocks, threads>>>(
        (const float4*)x, (const float4*)y, n4, out);
}